// round 6
// baseline (speedup 1.0000x reference)
#include <cuda_runtime.h>
#include <cuda_bf16.h>

#define LOG2E 1.4426950408889634f
typedef unsigned long long u64;

#define NCHK 16
#define CHKL 64

// ---------------- scratch (__device__ globals; no allocation allowed) -------
__device__ float g_xn  [32*1024*64];
__device__ float g_z   [32*1024*128];
__device__ float g_xc  [32*1024*128];
__device__ float g_dt  [32*1024*128];
__device__ float g_Bm  [32*1024*16];
__device__ float g_Cm  [32*1024*16];
__device__ float g_pend[32*NCHK*128*16];
__device__ float g_dtot[32*NCHK*128*16];
__device__ float g_h0  [32*NCHK*128*16];

__device__ __forceinline__ float ex2f(float x) {
    float r; asm("ex2.approx.f32 %0, %1;" : "=f"(r) : "f"(x)); return r;
}
__device__ __forceinline__ float siluf(float x) {
    return x / (1.0f + __expf(-x));
}
// helper: detect a2[s] == (s+1)*a2[0] (true for this problem's A_log)
__device__ __forceinline__ bool ratio_fast(const float* a2) {
    bool ok = true;
    #pragma unroll
    for (int s = 1; s < 16; s++) {
        float want = (float)(s + 1) * a2[0];
        ok = ok && (fabsf(a2[s] - want) <= 1e-3f * fabsf(want));
    }
    return ok;
}
// dA[s] = p^(s+1): exponents of dA[(s-1)>>1] and dA[s>>1] sum to s+1
__device__ __forceinline__ void powers16(float p, float* dA) {
    dA[0] = p;
    #pragma unroll
    for (int s = 1; s < 16; s++) dA[s] = dA[(s-1) >> 1] * dA[s >> 1];
}

// ========== KA: LayerNorm + W_in GEMM + conv4/SiLU + x_proj + dt ============
// grid = 32 seq * 32 tiles (32 tokens + 3 halo), block = 128, dynamic smem
__global__ void __launch_bounds__(128) kA_front(
    const float* __restrict__ x0, const float* __restrict__ x1,
    const float* __restrict__ x2, const float* __restrict__ x3,
    const float* __restrict__ ga, const float* __restrict__ gb,
    const float* __restrict__ gc, const float* __restrict__ gd,
    const float* __restrict__ ba, const float* __restrict__ bb,
    const float* __restrict__ bc_, const float* __restrict__ bd,
    const float* __restrict__ W_in,
    const float* __restrict__ W_conv, const float* __restrict__ b_conv,
    const float* __restrict__ W_xproj, const float* __restrict__ W_dt,
    const float* __restrict__ b_dt)
{
    extern __shared__ float sm[];
    float* xs    = sm;                  // [35][65]
    float* stat  = xs + 35*65;          // [35][2] (+pad)
    float* Wsh   = stat + 72;           // [128][65]  (reused for W_xproj^T [128][37])
    float* xis   = Wsh + 128*65;        // [35][128]
    float* xcs   = xis + 35*128;        // [32][128]
    float* res36 = xcs + 32*128;        // [32][36]

    int tid = threadIdx.x;
    int blk = blockIdx.x;
    int seq = blk >> 5;
    int l0  = (blk & 31) * 32;
    int br  = seq >> 3;
    int b   = seq & 7;

    const float* xp = (br == 0) ? x0 : (br == 1) ? x1 : (br == 2) ? x2 : x3;
    const float* gp = (br == 0) ? ga : (br == 1) ? gb : (br == 2) ? gc : gd;
    const float* bp = (br == 0) ? ba : (br == 1) ? bb : (br == 2) ? bc_ : bd;

    // ---- load 35 tokens x 64 channels (3-token halo), coalesced over l ----
    for (int idx = tid; idx < 35*64; idx += 128) {
        int t = idx % 35, c = idx / 35;
        int tl = l0 - 3 + t;
        xs[t*65 + c] = (tl >= 0) ? xp[(size_t)(b*64 + c)*1024 + tl] : 0.f;
    }
    __syncthreads();
    if (tid < 35) {
        float s = 0.f, s2 = 0.f;
        #pragma unroll 8
        for (int c = 0; c < 64; c++) { float v = xs[tid*65 + c]; s += v; s2 += v*v; }
        float m = s * (1.0f/64.0f);
        float var = s2 * (1.0f/64.0f) - m*m;
        stat[tid*2]   = m;
        stat[tid*2+1] = rsqrtf(var + 1e-5f);
    }
    __syncthreads();
    for (int idx = tid; idx < 35*64; idx += 128) {
        int c = idx & 63, t = idx >> 6;
        float v = (xs[t*65 + c] - stat[t*2]) * stat[t*2+1] * gp[c] + bp[c];
        xs[t*65 + c] = v;
        if (t >= 3) g_xn[(size_t)(seq*1024 + l0 - 3 + t)*64 + c] = v;
    }

    int tg = tid >> 5, jg = tid & 31;

    // ---- GEMM half 0: xi for 35 tokens -> xis smem (zero-masked halo) ----
    __syncthreads();
    for (int idx = tid; idx < 8192; idx += 128) {
        int c = idx & 63, jj = idx >> 6;
        Wsh[jj*65 + c] = W_in[(size_t)jj*64 + c];
    }
    __syncthreads();
    {
        int t0 = tg * 9;
        int nt = (tg < 3) ? 9 : 8;
        float acc[9][4];
        #pragma unroll
        for (int i = 0; i < 9; i++)
            #pragma unroll
            for (int u = 0; u < 4; u++) acc[i][u] = 0.f;
        #pragma unroll 4
        for (int k = 0; k < 64; k++) {
            float xv[9];
            #pragma unroll
            for (int i = 0; i < 9; i++) {
                int t = t0 + i; if (t > 34) t = 34;
                xv[i] = xs[t*65 + k];
            }
            #pragma unroll
            for (int u = 0; u < 4; u++) {
                float w = Wsh[(jg + 32*u)*65 + k];
                #pragma unroll
                for (int i = 0; i < 9; i++) acc[i][u] = fmaf(xv[i], w, acc[i][u]);
            }
        }
        for (int i = 0; i < 9; i++) {
            int t = t0 + i;
            if (i < nt) {
                bool valid = (l0 - 3 + t) >= 0;
                #pragma unroll
                for (int u = 0; u < 4; u++)
                    xis[t*128 + jg + 32*u] = valid ? acc[i][u] : 0.f;
            }
        }
    }

    // ---- GEMM half 1: z for the 32 main tokens -> global ----
    __syncthreads();
    for (int idx = tid; idx < 8192; idx += 128) {
        int c = idx & 63, jj = idx >> 6;
        Wsh[jj*65 + c] = W_in[(size_t)(128 + jj)*64 + c];
    }
    __syncthreads();
    {
        float acc[8][4];
        #pragma unroll
        for (int i = 0; i < 8; i++)
            #pragma unroll
            for (int u = 0; u < 4; u++) acc[i][u] = 0.f;
        #pragma unroll 4
        for (int k = 0; k < 64; k++) {
            float xv[8];
            #pragma unroll
            for (int i = 0; i < 8; i++) xv[i] = xs[(3 + tg*8 + i)*65 + k];
            #pragma unroll
            for (int u = 0; u < 4; u++) {
                float w = Wsh[(jg + 32*u)*65 + k];
                #pragma unroll
                for (int i = 0; i < 8; i++) acc[i][u] = fmaf(xv[i], w, acc[i][u]);
            }
        }
        #pragma unroll
        for (int i = 0; i < 8; i++) {
            int tt = tg*8 + i;
            #pragma unroll
            for (int u = 0; u < 4; u++)
                g_z[(size_t)(seq*1024 + l0 + tt)*128 + jg + 32*u] = acc[i][u];
        }
    }
    __syncthreads();

    // ---- conv4 + SiLU (thread = channel d) ; also load W_xproj^T ----
    {
        int d = tid;
        float wc0 = W_conv[d*4+0], wc1 = W_conv[d*4+1], wc2 = W_conv[d*4+2], wc3 = W_conv[d*4+3];
        float bcv = b_conv[d];
        #pragma unroll 4
        for (int t = 0; t < 32; t++) {
            float v = bcv + wc0*xis[t*128 + d] + wc1*xis[(t+1)*128 + d]
                          + wc2*xis[(t+2)*128 + d] + wc3*xis[(t+3)*128 + d];
            v = siluf(v);
            xcs[t*128 + d] = v;
            g_xc[(size_t)(seq*1024 + l0 + t)*128 + d] = v;
        }
    }
    for (int idx = tid; idx < 36*128; idx += 128) {
        int dd = idx & 127, j = idx >> 7;
        Wsh[dd*37 + j] = W_xproj[(size_t)j*128 + dd];
    }
    __syncthreads();

    // ---- x_proj: 32 tokens x 36 outputs ----
    for (int p = tid; p < 576; p += 128) {
        int tok = p / 18;
        int j0 = (p - tok*18) * 2;
        float a0 = 0.f, a1 = 0.f;
        #pragma unroll 16
        for (int dd = 0; dd < 128; dd++) {
            float xv = xcs[tok*128 + dd];
            a0 = fmaf(xv, Wsh[dd*37 + j0],     a0);
            a1 = fmaf(xv, Wsh[dd*37 + j0 + 1], a1);
        }
        res36[tok*36 + j0]     = a0;
        res36[tok*36 + j0 + 1] = a1;
    }
    __syncthreads();

    // ---- dt = softplus(dtp @ W_dt + b_dt) ; B/C scatter ----
    {
        int d = tid;
        float wd0 = W_dt[d*4+0], wd1 = W_dt[d*4+1], wd2 = W_dt[d*4+2], wd3 = W_dt[d*4+3];
        float bdv = b_dt[d];
        #pragma unroll 4
        for (int t = 0; t < 32; t++) {
            float raw = bdv + wd0*res36[t*36+0] + wd1*res36[t*36+1]
                            + wd2*res36[t*36+2] + wd3*res36[t*36+3];
            float sp = fmaxf(raw, 0.f) + log1pf(__expf(-fabsf(raw)));
            g_dt[(size_t)(seq*1024 + l0 + t)*128 + d] = sp;
        }
    }
    for (int idx = tid; idx < 1024; idx += 128) {
        int tok = idx >> 5, q = idx & 31;
        float v = res36[tok*36 + 4 + q];
        if (q < 16) g_Bm[(size_t)(seq*1024 + l0 + tok)*16 + q]        = v;
        else        g_Cm[(size_t)(seq*1024 + l0 + tok)*16 + (q - 16)] = v;
    }
}

// ============== K3: per-chunk scan summaries (h0 = 0) =======================
// grid = 512 (seq*NCHK + chunk), block = 128 (thread = channel d)
__global__ void __launch_bounds__(128) k3_chunk(const float* __restrict__ A_log)
{
    __shared__ float Bs[CHKL*16];
    int tid = threadIdx.x;
    int blk = blockIdx.x;
    int seq = blk >> 4;
    int ck  = blk & (NCHK-1);
    int c0  = ck * CHKL;

    for (int idx = tid; idx < CHKL*16; idx += 128)
        Bs[idx] = g_Bm[(size_t)(seq*1024 + c0)*16 + idx];
    __syncthreads();

    int d = tid;
    float a2[16];
    #pragma unroll
    for (int s = 0; s < 16; s++) a2[s] = -__expf(A_log[d*16 + s]) * LOG2E;
    bool fast = ratio_fast(a2);

    const float* dtp_ = g_dt + (size_t)(seq*1024 + c0)*128 + d;
    const float* xcp_ = g_xc + (size_t)(seq*1024 + c0)*128 + d;
    float sdt = 0.f;
    float h[16];
    #pragma unroll
    for (int s = 0; s < 16; s++) h[s] = 0.f;

    if (fast) {
        const float4* B4 = (const float4*)Bs;
        float pdt[4], pxc[4];
        #pragma unroll
        for (int j = 0; j < 4; j++) { pdt[j] = dtp_[j*128]; pxc[j] = xcp_[j*128]; }
        for (int t0 = 0; t0 < CHKL; t0 += 4) {
            float ndt[4], nxc[4];
            #pragma unroll
            for (int j = 0; j < 4; j++) {
                int tn = t0 + 4 + j;
                if (tn < CHKL) { ndt[j] = dtp_[tn*128]; nxc[j] = xcp_[tn*128]; }
                else           { ndt[j] = 0.f;          nxc[j] = 0.f; }
            }
            #pragma unroll
            for (int j = 0; j < 4; j++) {
                int t = t0 + j;
                sdt += pdt[j];
                float dx = pdt[j] * pxc[j];
                float p = ex2f(pdt[j] * a2[0]);
                float dA[16]; powers16(p, dA);
                float4 b0 = B4[t*4+0], b1 = B4[t*4+1], b2 = B4[t*4+2], b3 = B4[t*4+3];
                const float bl[16] = {b0.x,b0.y,b0.z,b0.w, b1.x,b1.y,b1.z,b1.w,
                                      b2.x,b2.y,b2.z,b2.w, b3.x,b3.y,b3.z,b3.w};
                #pragma unroll
                for (int s = 0; s < 16; s++)
                    h[s] = fmaf(dA[s], h[s], dx * bl[s]);
            }
            #pragma unroll
            for (int j = 0; j < 4; j++) { pdt[j] = ndt[j]; pxc[j] = nxc[j]; }
        }
    } else {
        for (int t = 0; t < CHKL; t++) {
            float dtv = dtp_[t*128], xcv = xcp_[t*128];
            sdt += dtv;
            float dx = dtv * xcv;
            #pragma unroll
            for (int s = 0; s < 16; s++) {
                float dA = ex2f(dtv * a2[s]);
                h[s] = fmaf(dA, h[s], dx * Bs[t*16 + s]);
            }
        }
    }
    size_t base = ((size_t)(seq*NCHK + ck)*128 + d)*16;
    #pragma unroll
    for (int s = 0; s < 16; s++) {
        g_pend[base + s] = h[s];
        g_dtot[base + s] = ex2f(a2[s] * sdt);
    }
}

// ============== K4: sequential combine of chunk states ======================
__global__ void __launch_bounds__(256) k4_combine()
{
    int blk = blockIdx.x;
    int seq = blk >> 3;
    int pair = (blk & 7) * 256 + threadIdx.x;
    float dtv[NCHK], pev[NCHK];
    #pragma unroll
    for (int k = 0; k < NCHK; k++) {
        size_t o = (size_t)(seq*NCHK + k)*2048 + pair;
        dtv[k] = g_dtot[o];
        pev[k] = g_pend[o];
    }
    float h = 0.f;
    #pragma unroll
    for (int k = 0; k < NCHK; k++) {
        g_h0[(size_t)(seq*NCHK + k)*2048 + pair] = h;
        h = fmaf(dtv[k], h, pev[k]);
    }
}

// ====== KB: scan + y epilogue + W_out GEMM + skip + transposed output =======
// grid = 512 (seq*NCHK + chunk), block = 128 (thread = channel d), dyn smem
__global__ void __launch_bounds__(128) kB_scan_out(
    const float* __restrict__ A_log, const float* __restrict__ Dp,
    const float* __restrict__ W_out, const float* __restrict__ skip,
    float* __restrict__ out)
{
    extern __shared__ float sm[];
    float* Bs  = sm;                 // [64][16]
    float* Cs  = Bs + CHKL*16;       // [64][16]
    float* ys  = Cs + CHKL*16;       // [64 t][129]  (reused as os [64 c][65])
    float* Wsh = ys + 64*129;        // [128 k][65 c]

    int tid = threadIdx.x;
    int blk = blockIdx.x;
    int seq = blk >> 4;
    int ck  = blk & (NCHK-1);
    int c0  = ck * CHKL;
    int br  = seq >> 3;
    int b   = seq & 7;

    for (int idx = tid; idx < CHKL*16; idx += 128) {
        Bs[idx] = g_Bm[(size_t)(seq*1024 + c0)*16 + idx];
        Cs[idx] = g_Cm[(size_t)(seq*1024 + c0)*16 + idx];
    }
    for (int idx = tid; idx < 64*128; idx += 128) {
        int c = idx >> 7, k = idx & 127;
        Wsh[k*65 + c] = W_out[(size_t)c*128 + k];
    }
    __syncthreads();

    int d = tid;
    float a2[16];
    #pragma unroll
    for (int s = 0; s < 16; s++) a2[s] = -__expf(A_log[d*16 + s]) * LOG2E;
    bool fast = ratio_fast(a2);
    float Dv = Dp[d];

    float h[16];
    size_t hb = ((size_t)(seq*NCHK + ck)*128 + d)*16;
    #pragma unroll
    for (int s = 0; s < 16; s++) h[s] = g_h0[hb + s];

    const float* dtp_ = g_dt + (size_t)(seq*1024 + c0)*128 + d;
    const float* xcp_ = g_xc + (size_t)(seq*1024 + c0)*128 + d;
    const float* zp_  = g_z  + (size_t)(seq*1024 + c0)*128 + d;

    if (fast) {
        const float4* B4 = (const float4*)Bs;
        const float4* C4 = (const float4*)Cs;
        float pdt[4], pxc[4], pz[4];
        #pragma unroll
        for (int j = 0; j < 4; j++) {
            pdt[j] = dtp_[j*128]; pxc[j] = xcp_[j*128]; pz[j] = zp_[j*128];
        }
        for (int t0 = 0; t0 < CHKL; t0 += 4) {
            float ndt[4], nxc[4], nz[4];
            #pragma unroll
            for (int j = 0; j < 4; j++) {
                int tn = t0 + 4 + j;
                if (tn < CHKL) { ndt[j] = dtp_[tn*128]; nxc[j] = xcp_[tn*128]; nz[j] = zp_[tn*128]; }
                else           { ndt[j] = 0.f; nxc[j] = 0.f; nz[j] = 0.f; }
            }
            #pragma unroll
            for (int j = 0; j < 4; j++) {
                int t = t0 + j;
                float dx = pdt[j] * pxc[j];
                float p = ex2f(pdt[j] * a2[0]);
                float dA[16]; powers16(p, dA);
                float4 b0 = B4[t*4+0], b1 = B4[t*4+1], b2 = B4[t*4+2], b3 = B4[t*4+3];
                float4 cc0 = C4[t*4+0], cc1 = C4[t*4+1], cc2 = C4[t*4+2], cc3 = C4[t*4+3];
                const float bl[16] = {b0.x,b0.y,b0.z,b0.w, b1.x,b1.y,b1.z,b1.w,
                                      b2.x,b2.y,b2.z,b2.w, b3.x,b3.y,b3.z,b3.w};
                const float cl[16] = {cc0.x,cc0.y,cc0.z,cc0.w, cc1.x,cc1.y,cc1.z,cc1.w,
                                      cc2.x,cc2.y,cc2.z,cc2.w, cc3.x,cc3.y,cc3.z,cc3.w};
                float y = 0.f;
                #pragma unroll
                for (int s = 0; s < 16; s++) {
                    h[s] = fmaf(dA[s], h[s], dx * bl[s]);
                    y = fmaf(h[s], cl[s], y);
                }
                ys[t*129 + d] = (y + Dv*pxc[j]) * siluf(pz[j]);
            }
            #pragma unroll
            for (int j = 0; j < 4; j++) { pdt[j] = ndt[j]; pxc[j] = nxc[j]; pz[j] = nz[j]; }
        }
    } else {
        for (int t = 0; t < CHKL; t++) {
            float dtv = dtp_[t*128], xcv = xcp_[t*128], zv = zp_[t*128];
            float dx = dtv * xcv;
            float y = 0.f;
            #pragma unroll
            for (int s = 0; s < 16; s++) {
                float dA = ex2f(dtv * a2[s]);
                h[s] = fmaf(dA, h[s], dx * Bs[t*16 + s]);
                y = fmaf(h[s], Cs[t*16 + s], y);
            }
            ys[t*129 + d] = (y + Dv*xcv) * siluf(zv);
        }
    }
    __syncthreads();

    // ---- W_out GEMM (64 tok x 64 out x 128 k) ----
    int tg = tid >> 4, jg = tid & 15;
    float acc[8][4];
    #pragma unroll
    for (int i = 0; i < 8; i++)
        #pragma unroll
        for (int u = 0; u < 4; u++) acc[i][u] = 0.f;
    #pragma unroll 4
    for (int k = 0; k < 128; k++) {
        float xv[8];
        #pragma unroll
        for (int i = 0; i < 8; i++) xv[i] = ys[(tg*8 + i)*129 + k];
        #pragma unroll
        for (int u = 0; u < 4; u++) {
            float w = Wsh[k*65 + jg + 16*u];
            #pragma unroll
            for (int i = 0; i < 8; i++) acc[i][u] = fmaf(xv[i], w, acc[i][u]);
        }
    }
    __syncthreads();
    float* os = ys;   // reuse: [c][t] pitch 65
    float sk = skip[0];
    #pragma unroll
    for (int u = 0; u < 4; u++)
        #pragma unroll
        for (int i = 0; i < 8; i++) {
            int t = tg*8 + i, c = jg + 16*u;
            float xnv = g_xn[(size_t)(seq*1024 + c0 + t)*64 + c];
            os[c*65 + t] = acc[i][u] + sk * xnv;
        }
    __syncthreads();
    for (int idx = tid; idx < 4096; idx += 128) {
        int c = idx >> 6, t = idx & 63;
        out[(size_t)(b*256 + br*64 + c)*1024 + c0 + t] = os[c*65 + t];
    }
}

// ============================== launch ======================================
extern "C" void kernel_launch(void* const* d_in, const int* in_sizes, int n_in,
                              void* d_out, int out_size) {
    const float* x0      = (const float*)d_in[0];
    const float* x1      = (const float*)d_in[1];
    const float* x2      = (const float*)d_in[2];
    const float* x3      = (const float*)d_in[3];
    const float* g1      = (const float*)d_in[4];
    const float* be1     = (const float*)d_in[5];
    const float* g2      = (const float*)d_in[6];
    const float* be2     = (const float*)d_in[7];
    const float* g3      = (const float*)d_in[8];
    const float* be3     = (const float*)d_in[9];
    const float* g4      = (const float*)d_in[10];
    const float* be4     = (const float*)d_in[11];
    const float* skip    = (const float*)d_in[12];
    const float* W_in    = (const float*)d_in[13];
    const float* W_conv  = (const float*)d_in[14];
    const float* b_conv  = (const float*)d_in[15];
    const float* W_xproj = (const float*)d_in[16];
    const float* W_dt    = (const float*)d_in[17];
    const float* b_dt    = (const float*)d_in[18];
    const float* A_log   = (const float*)d_in[19];
    const float* Dp      = (const float*)d_in[20];
    const float* W_out   = (const float*)d_in[21];
    float* out = (float*)d_out;

    const int SMEMA = (35*65 + 72 + 128*65 + 35*128 + 32*128 + 32*36) * (int)sizeof(float);
    const int SMEMB = (CHKL*16*2 + 64*129 + 128*65) * (int)sizeof(float);
    static bool configured = false;
    if (!configured) {
        cudaFuncSetAttribute(kA_front,
                             cudaFuncAttributeMaxDynamicSharedMemorySize, SMEMA);
        cudaFuncSetAttribute(kB_scan_out,
                             cudaFuncAttributeMaxDynamicSharedMemorySize, SMEMB);
        configured = true;
    }

    kA_front<<<1024, 128, SMEMA>>>(x0, x1, x2, x3, g1, g2, g3, g4,
                                   be1, be2, be3, be4, W_in,
                                   W_conv, b_conv, W_xproj, W_dt, b_dt);
    k3_chunk<<<512, 128>>>(A_log);
    k4_combine<<<256, 256>>>();
    kB_scan_out<<<512, 128, SMEMB>>>(A_log, Dp, W_out, skip, out);
}

// round 7
// speedup vs baseline: 1.2213x; 1.2213x over previous
#include <cuda_runtime.h>
#include <cuda_bf16.h>

#define LOG2E 1.4426950408889634f

#define NCHK 32
#define CHKL 32

// ---------------- scratch (__device__ globals; no allocation allowed) -------
__device__ float g_xn  [32*1024*64];
__device__ float g_z   [32*1024*128];
__device__ float g_xc  [32*1024*128];
__device__ float g_dt  [32*1024*128];
__device__ float g_Bm  [32*1024*16];
__device__ float g_Cm  [32*1024*16];
__device__ float g_pend[32*NCHK*128*16];
__device__ float g_dtot[32*NCHK*128*16];
__device__ float g_h0  [32*NCHK*128*16];

__device__ __forceinline__ float ex2f(float x) {
    float r; asm("ex2.approx.f32 %0, %1;" : "=f"(r) : "f"(x)); return r;
}
__device__ __forceinline__ float siluf(float x) {
    return x / (1.0f + __expf(-x));
}
// helper: detect a2[s] == (s+1)*a2[0] (true for this problem's A_log)
__device__ __forceinline__ bool ratio_fast(const float* a2) {
    bool ok = true;
    #pragma unroll
    for (int s = 1; s < 16; s++) {
        float want = (float)(s + 1) * a2[0];
        ok = ok && (fabsf(a2[s] - want) <= 1e-3f * fabsf(want));
    }
    return ok;
}
// dA[s] = p^(s+1): exponents of dA[(s-1)>>1] and dA[s>>1] sum to s+1
__device__ __forceinline__ void powers16(float p, float* dA) {
    dA[0] = p;
    #pragma unroll
    for (int s = 1; s < 16; s++) dA[s] = dA[(s-1) >> 1] * dA[s >> 1];
}

// == KA: LN + W_in GEMM + conv/SiLU + x_proj + dt + CHUNK SCAN SUMMARY =======
// grid = 32 seq * 32 chunks (32 tokens + 3 halo), block = 128, dynamic smem
__global__ void __launch_bounds__(128) kA_front(
    const float* __restrict__ x0, const float* __restrict__ x1,
    const float* __restrict__ x2, const float* __restrict__ x3,
    const float* __restrict__ ga, const float* __restrict__ gb,
    const float* __restrict__ gc, const float* __restrict__ gd,
    const float* __restrict__ ba, const float* __restrict__ bb,
    const float* __restrict__ bc_, const float* __restrict__ bd,
    const float* __restrict__ W_in,
    const float* __restrict__ W_conv, const float* __restrict__ b_conv,
    const float* __restrict__ W_xproj, const float* __restrict__ W_dt,
    const float* __restrict__ b_dt, const float* __restrict__ A_log)
{
    extern __shared__ float sm[];
    float* xs    = sm;                  // [35][65]
    float* stat  = xs + 35*65;          // [35][2] (+pad)
    float* Wsh   = stat + 72;           // [128][65] (reused for W_xproj^T [128][37])
    float* xis   = Wsh + 128*65;        // [35][128]; rows 0..31 become xc in-place
    float* res36 = xis + 35*128;        // [32][36]

    int tid = threadIdx.x;
    int blk = blockIdx.x;
    int seq = blk >> 5;
    int ck  = blk & 31;
    int l0  = ck * 32;
    int br  = seq >> 3;
    int b   = seq & 7;

    const float* xp = (br == 0) ? x0 : (br == 1) ? x1 : (br == 2) ? x2 : x3;
    const float* gp = (br == 0) ? ga : (br == 1) ? gb : (br == 2) ? gc : gd;
    const float* bp = (br == 0) ? ba : (br == 1) ? bb : (br == 2) ? bc_ : bd;

    // ---- load 35 tokens x 64 channels (3-token halo) ----
    for (int idx = tid; idx < 35*64; idx += 128) {
        int t = idx % 35, c = idx / 35;
        int tl = l0 - 3 + t;
        xs[t*65 + c] = (tl >= 0) ? xp[(size_t)(b*64 + c)*1024 + tl] : 0.f;
    }
    __syncthreads();
    if (tid < 35) {
        float s = 0.f, s2 = 0.f;
        #pragma unroll 8
        for (int c = 0; c < 64; c++) { float v = xs[tid*65 + c]; s += v; s2 += v*v; }
        float m = s * (1.0f/64.0f);
        float var = s2 * (1.0f/64.0f) - m*m;
        stat[tid*2]   = m;
        stat[tid*2+1] = rsqrtf(var + 1e-5f);
    }
    __syncthreads();
    for (int idx = tid; idx < 35*64; idx += 128) {
        int c = idx & 63, t = idx >> 6;
        float v = (xs[t*65 + c] - stat[t*2]) * stat[t*2+1] * gp[c] + bp[c];
        xs[t*65 + c] = v;
        if (t >= 3) g_xn[(size_t)(seq*1024 + l0 - 3 + t)*64 + c] = v;
    }

    int tg = tid >> 5, jg = tid & 31;

    // ---- GEMM half 0: xi for 35 tokens -> xis smem (zero-masked halo) ----
    __syncthreads();
    for (int idx = tid; idx < 8192; idx += 128) {
        int c = idx & 63, jj = idx >> 6;
        Wsh[jj*65 + c] = W_in[(size_t)jj*64 + c];
    }
    __syncthreads();
    {
        int t0 = tg * 9;
        int nt = (tg < 3) ? 9 : 8;
        float acc[9][4];
        #pragma unroll
        for (int i = 0; i < 9; i++)
            #pragma unroll
            for (int u = 0; u < 4; u++) acc[i][u] = 0.f;
        #pragma unroll 4
        for (int k = 0; k < 64; k++) {
            float xv[9];
            #pragma unroll
            for (int i = 0; i < 9; i++) {
                int t = t0 + i; if (t > 34) t = 34;
                xv[i] = xs[t*65 + k];
            }
            #pragma unroll
            for (int u = 0; u < 4; u++) {
                float w = Wsh[(jg + 32*u)*65 + k];
                #pragma unroll
                for (int i = 0; i < 9; i++) acc[i][u] = fmaf(xv[i], w, acc[i][u]);
            }
        }
        for (int i = 0; i < 9; i++) {
            int t = t0 + i;
            if (i < nt) {
                bool valid = (l0 - 3 + t) >= 0;
                #pragma unroll
                for (int u = 0; u < 4; u++)
                    xis[t*128 + jg + 32*u] = valid ? acc[i][u] : 0.f;
            }
        }
    }

    // ---- GEMM half 1: z for the 32 main tokens -> global ----
    __syncthreads();
    for (int idx = tid; idx < 8192; idx += 128) {
        int c = idx & 63, jj = idx >> 6;
        Wsh[jj*65 + c] = W_in[(size_t)(128 + jj)*64 + c];
    }
    __syncthreads();
    {
        float acc[8][4];
        #pragma unroll
        for (int i = 0; i < 8; i++)
            #pragma unroll
            for (int u = 0; u < 4; u++) acc[i][u] = 0.f;
        #pragma unroll 4
        for (int k = 0; k < 64; k++) {
            float xv[8];
            #pragma unroll
            for (int i = 0; i < 8; i++) xv[i] = xs[(3 + tg*8 + i)*65 + k];
            #pragma unroll
            for (int u = 0; u < 4; u++) {
                float w = Wsh[(jg + 32*u)*65 + k];
                #pragma unroll
                for (int i = 0; i < 8; i++) acc[i][u] = fmaf(xv[i], w, acc[i][u]);
            }
        }
        #pragma unroll
        for (int i = 0; i < 8; i++) {
            int tt = tg*8 + i;
            #pragma unroll
            for (int u = 0; u < 4; u++)
                g_z[(size_t)(seq*1024 + l0 + tt)*128 + jg + 32*u] = acc[i][u];
        }
    }
    __syncthreads();

    // ---- conv4 + SiLU, in place: row t of xis becomes xc[t] ----
    {
        int d = tid;
        float wc0 = W_conv[d*4+0], wc1 = W_conv[d*4+1], wc2 = W_conv[d*4+2], wc3 = W_conv[d*4+3];
        float bcv = b_conv[d];
        #pragma unroll 4
        for (int t = 0; t < 32; t++) {
            float v = bcv + wc0*xis[t*128 + d] + wc1*xis[(t+1)*128 + d]
                          + wc2*xis[(t+2)*128 + d] + wc3*xis[(t+3)*128 + d];
            v = siluf(v);
            xis[t*128 + d] = v;   // safe: row t read only by iterations <= t
            g_xc[(size_t)(seq*1024 + l0 + t)*128 + d] = v;
        }
    }
    __syncthreads();
    for (int idx = tid; idx < 36*128; idx += 128) {
        int dd = idx & 127, j = idx >> 7;
        Wsh[dd*37 + j] = W_xproj[(size_t)j*128 + dd];
    }
    __syncthreads();

    // ---- x_proj: 32 tokens x 36 outputs ----
    for (int p = tid; p < 576; p += 128) {
        int tok = p / 18;
        int j0 = (p - tok*18) * 2;
        float a0 = 0.f, a1 = 0.f;
        #pragma unroll 16
        for (int dd = 0; dd < 128; dd++) {
            float xv = xis[tok*128 + dd];
            a0 = fmaf(xv, Wsh[dd*37 + j0],     a0);
            a1 = fmaf(xv, Wsh[dd*37 + j0 + 1], a1);
        }
        res36[tok*36 + j0]     = a0;
        res36[tok*36 + j0 + 1] = a1;
    }
    __syncthreads();

    // ---- fused: dt(softplus) + chunk scan summary (h0 = 0) ----
    {
        int d = tid;
        float wd0 = W_dt[d*4+0], wd1 = W_dt[d*4+1], wd2 = W_dt[d*4+2], wd3 = W_dt[d*4+3];
        float bdv = b_dt[d];
        float a2[16];
        #pragma unroll
        for (int s = 0; s < 16; s++) a2[s] = -__expf(A_log[d*16 + s]) * LOG2E;
        bool fast = ratio_fast(a2);
        float h[16];
        #pragma unroll
        for (int s = 0; s < 16; s++) h[s] = 0.f;
        float sdt = 0.f;

        if (fast) {
            for (int t = 0; t < 32; t++) {
                float raw = bdv + wd0*res36[t*36+0] + wd1*res36[t*36+1]
                                + wd2*res36[t*36+2] + wd3*res36[t*36+3];
                float sp = fmaxf(raw, 0.f) + log1pf(__expf(-fabsf(raw)));
                g_dt[(size_t)(seq*1024 + l0 + t)*128 + d] = sp;
                sdt += sp;
                float dx = sp * xis[t*128 + d];
                float p = ex2f(sp * a2[0]);
                float dA[16]; powers16(p, dA);
                #pragma unroll
                for (int s = 0; s < 16; s++)
                    h[s] = fmaf(dA[s], h[s], dx * res36[t*36 + 4 + s]);
            }
        } else {
            for (int t = 0; t < 32; t++) {
                float raw = bdv + wd0*res36[t*36+0] + wd1*res36[t*36+1]
                                + wd2*res36[t*36+2] + wd3*res36[t*36+3];
                float sp = fmaxf(raw, 0.f) + log1pf(__expf(-fabsf(raw)));
                g_dt[(size_t)(seq*1024 + l0 + t)*128 + d] = sp;
                sdt += sp;
                float dx = sp * xis[t*128 + d];
                #pragma unroll
                for (int s = 0; s < 16; s++) {
                    float dA = ex2f(sp * a2[s]);
                    h[s] = fmaf(dA, h[s], dx * res36[t*36 + 4 + s]);
                }
            }
        }
        size_t base = ((size_t)(seq*NCHK + ck)*128 + d)*16;
        if (fast) {
            float p = ex2f(a2[0] * sdt);
            float dA[16]; powers16(p, dA);
            #pragma unroll
            for (int s = 0; s < 16; s++) {
                g_pend[base + s] = h[s];
                g_dtot[base + s] = dA[s];
            }
        } else {
            #pragma unroll
            for (int s = 0; s < 16; s++) {
                g_pend[base + s] = h[s];
                g_dtot[base + s] = ex2f(a2[s] * sdt);
            }
        }
    }

    // ---- B/C scatter ----
    for (int idx = tid; idx < 1024; idx += 128) {
        int tok = idx >> 5, q = idx & 31;
        float v = res36[tok*36 + 4 + q];
        if (q < 16) g_Bm[(size_t)(seq*1024 + l0 + tok)*16 + q]        = v;
        else        g_Cm[(size_t)(seq*1024 + l0 + tok)*16 + (q - 16)] = v;
    }
}

// ============== K4: sequential combine of chunk states ======================
// grid = 256 (seq*8), block = 256; one thread per (seq, pair); two 16-batches
__global__ void __launch_bounds__(256) k4_combine()
{
    int blk = blockIdx.x;
    int seq = blk >> 3;
    int pair = (blk & 7) * 256 + threadIdx.x;
    float h = 0.f;
    #pragma unroll
    for (int half = 0; half < 2; half++) {
        float dtv[16], pev[16];
        #pragma unroll
        for (int k = 0; k < 16; k++) {
            size_t o = (size_t)(seq*NCHK + half*16 + k)*2048 + pair;
            dtv[k] = g_dtot[o];
            pev[k] = g_pend[o];
        }
        #pragma unroll
        for (int k = 0; k < 16; k++) {
            g_h0[(size_t)(seq*NCHK + half*16 + k)*2048 + pair] = h;
            h = fmaf(dtv[k], h, pev[k]);
        }
    }
}

// ====== KB: scan + y epilogue + W_out GEMM + skip + transposed output =======
// grid = 1024 (seq*NCHK + chunk), block = 128 (thread = channel d), dyn smem
__global__ void __launch_bounds__(128) kB_scan_out(
    const float* __restrict__ A_log, const float* __restrict__ Dp,
    const float* __restrict__ W_out, const float* __restrict__ skip,
    float* __restrict__ out)
{
    extern __shared__ float sm[];
    float* Bs  = sm;                 // [32][16]
    float* Cs  = Bs + CHKL*16;       // [32][16]
    float* ys  = Cs + CHKL*16;       // [32 t][129]  (reused as os [64 c][33])
    float* Wsh = ys + 32*129;        // [128 k][65 c]

    int tid = threadIdx.x;
    int blk = blockIdx.x;
    int seq = blk >> 5;
    int ck  = blk & 31;
    int c0  = ck * CHKL;
    int br  = seq >> 3;
    int b   = seq & 7;

    for (int idx = tid; idx < CHKL*16; idx += 128) {
        Bs[idx] = g_Bm[(size_t)(seq*1024 + c0)*16 + idx];
        Cs[idx] = g_Cm[(size_t)(seq*1024 + c0)*16 + idx];
    }
    for (int idx = tid; idx < 64*128; idx += 128) {
        int c = idx >> 7, k = idx & 127;
        Wsh[k*65 + c] = W_out[(size_t)c*128 + k];
    }
    __syncthreads();

    int d = tid;
    float a2[16];
    #pragma unroll
    for (int s = 0; s < 16; s++) a2[s] = -__expf(A_log[d*16 + s]) * LOG2E;
    bool fast = ratio_fast(a2);
    float Dv = Dp[d];

    float h[16];
    size_t hb = ((size_t)(seq*NCHK + ck)*128 + d)*16;
    #pragma unroll
    for (int s = 0; s < 16; s++) h[s] = g_h0[hb + s];

    const float* dtp_ = g_dt + (size_t)(seq*1024 + c0)*128 + d;
    const float* xcp_ = g_xc + (size_t)(seq*1024 + c0)*128 + d;
    const float* zp_  = g_z  + (size_t)(seq*1024 + c0)*128 + d;

    if (fast) {
        const float4* B4 = (const float4*)Bs;
        const float4* C4 = (const float4*)Cs;
        float pdt[4], pxc[4], pz[4];
        #pragma unroll
        for (int j = 0; j < 4; j++) {
            pdt[j] = dtp_[j*128]; pxc[j] = xcp_[j*128]; pz[j] = zp_[j*128];
        }
        for (int t0 = 0; t0 < CHKL; t0 += 4) {
            float ndt[4], nxc[4], nz[4];
            #pragma unroll
            for (int j = 0; j < 4; j++) {
                int tn = t0 + 4 + j;
                if (tn < CHKL) { ndt[j] = dtp_[tn*128]; nxc[j] = xcp_[tn*128]; nz[j] = zp_[tn*128]; }
                else           { ndt[j] = 0.f; nxc[j] = 0.f; nz[j] = 0.f; }
            }
            #pragma unroll
            for (int j = 0; j < 4; j++) {
                int t = t0 + j;
                float dx = pdt[j] * pxc[j];
                float p = ex2f(pdt[j] * a2[0]);
                float dA[16]; powers16(p, dA);
                float4 b0 = B4[t*4+0], b1 = B4[t*4+1], b2 = B4[t*4+2], b3 = B4[t*4+3];
                float4 cc0 = C4[t*4+0], cc1 = C4[t*4+1], cc2 = C4[t*4+2], cc3 = C4[t*4+3];
                const float bl[16] = {b0.x,b0.y,b0.z,b0.w, b1.x,b1.y,b1.z,b1.w,
                                      b2.x,b2.y,b2.z,b2.w, b3.x,b3.y,b3.z,b3.w};
                const float cl[16] = {cc0.x,cc0.y,cc0.z,cc0.w, cc1.x,cc1.y,cc1.z,cc1.w,
                                      cc2.x,cc2.y,cc2.z,cc2.w, cc3.x,cc3.y,cc3.z,cc3.w};
                float y = 0.f;
                #pragma unroll
                for (int s = 0; s < 16; s++) {
                    h[s] = fmaf(dA[s], h[s], dx * bl[s]);
                    y = fmaf(h[s], cl[s], y);
                }
                ys[t*129 + d] = (y + Dv*pxc[j]) * siluf(pz[j]);
            }
            #pragma unroll
            for (int j = 0; j < 4; j++) { pdt[j] = ndt[j]; pxc[j] = nxc[j]; pz[j] = nz[j]; }
        }
    } else {
        for (int t = 0; t < CHKL; t++) {
            float dtv = dtp_[t*128], xcv = xcp_[t*128], zv = zp_[t*128];
            float dx = dtv * xcv;
            float y = 0.f;
            #pragma unroll
            for (int s = 0; s < 16; s++) {
                float dA = ex2f(dtv * a2[s]);
                h[s] = fmaf(dA, h[s], dx * Bs[t*16 + s]);
                y = fmaf(h[s], Cs[t*16 + s], y);
            }
            ys[t*129 + d] = (y + Dv*xcv) * siluf(zv);
        }
    }
    __syncthreads();

    // ---- W_out GEMM (32 tok x 64 out x 128 k) ----
    int tg = tid >> 4, jg = tid & 15;   // 8 groups x 4 tokens; 16 x 4 outputs
    float acc[4][4];
    #pragma unroll
    for (int i = 0; i < 4; i++)
        #pragma unroll
        for (int u = 0; u < 4; u++) acc[i][u] = 0.f;
    #pragma unroll 4
    for (int k = 0; k < 128; k++) {
        float xv[4];
        #pragma unroll
        for (int i = 0; i < 4; i++) xv[i] = ys[(tg*4 + i)*129 + k];
        #pragma unroll
        for (int u = 0; u < 4; u++) {
            float w = Wsh[k*65 + jg + 16*u];
            #pragma unroll
            for (int i = 0; i < 4; i++) acc[i][u] = fmaf(xv[i], w, acc[i][u]);
        }
    }
    __syncthreads();
    float* os = ys;   // reuse: [c][t] pitch 33
    float sk = skip[0];
    #pragma unroll
    for (int u = 0; u < 4; u++)
        #pragma unroll
        for (int i = 0; i < 4; i++) {
            int t = tg*4 + i, c = jg + 16*u;
            float xnv = g_xn[(size_t)(seq*1024 + c0 + t)*64 + c];
            os[c*33 + t] = acc[i][u] + sk * xnv;
        }
    __syncthreads();
    for (int idx = tid; idx < 2048; idx += 128) {
        int c = idx >> 5, t = idx & 31;
        out[(size_t)(b*256 + br*64 + c)*1024 + c0 + t] = os[c*33 + t];
    }
}

// ============================== launch ======================================
extern "C" void kernel_launch(void* const* d_in, const int* in_sizes, int n_in,
                              void* d_out, int out_size) {
    const float* x0      = (const float*)d_in[0];
    const float* x1      = (const float*)d_in[1];
    const float* x2      = (const float*)d_in[2];
    const float* x3      = (const float*)d_in[3];
    const float* g1      = (const float*)d_in[4];
    const float* be1     = (const float*)d_in[5];
    const float* g2      = (const float*)d_in[6];
    const float* be2     = (const float*)d_in[7];
    const float* g3      = (const float*)d_in[8];
    const float* be3     = (const float*)d_in[9];
    const float* g4      = (const float*)d_in[10];
    const float* be4     = (const float*)d_in[11];
    const float* skip    = (const float*)d_in[12];
    const float* W_in    = (const float*)d_in[13];
    const float* W_conv  = (const float*)d_in[14];
    const float* b_conv  = (const float*)d_in[15];
    const float* W_xproj = (const float*)d_in[16];
    const float* W_dt    = (const float*)d_in[17];
    const float* b_dt    = (const float*)d_in[18];
    const float* A_log   = (const float*)d_in[19];
    const float* Dp      = (const float*)d_in[20];
    const float* W_out   = (const float*)d_in[21];
    float* out = (float*)d_out;

    const int SMEMA = (35*65 + 72 + 128*65 + 35*128 + 32*36) * (int)sizeof(float);
    const int SMEMB = (CHKL*16*2 + 32*129 + 128*65) * (int)sizeof(float);
    static bool configured = false;
    if (!configured) {
        cudaFuncSetAttribute(kA_front,
                             cudaFuncAttributeMaxDynamicSharedMemorySize, SMEMA);
        cudaFuncSetAttribute(kB_scan_out,
                             cudaFuncAttributeMaxDynamicSharedMemorySize, SMEMB);
        configured = true;
    }

    kA_front<<<1024, 128, SMEMA>>>(x0, x1, x2, x3, g1, g2, g3, g4,
                                   be1, be2, be3, be4, W_in,
                                   W_conv, b_conv, W_xproj, W_dt, b_dt, A_log);
    k4_combine<<<256, 256>>>();
    kB_scan_out<<<1024, 128, SMEMB>>>(A_log, Dp, W_out, skip, out);
}

// round 8
// speedup vs baseline: 1.4546x; 1.1909x over previous
#include <cuda_runtime.h>
#include <cuda_bf16.h>

#define LOG2E 1.4426950408889634f

#define NCHK 32
#define CHKL 32

// ---------------- scratch (__device__ globals; no allocation allowed) -------
__device__ float g_xn  [32*1024*64];
__device__ float g_z   [32*1024*128];
__device__ float g_xc  [32*1024*128];
__device__ float g_dt  [32*1024*128];
__device__ float g_Bm  [32*1024*16];
__device__ float g_Cm  [32*1024*16];
__device__ float g_pend[32*NCHK*128*16];
__device__ float g_dtot[32*NCHK*128*16];
__device__ float g_h0  [32*NCHK*128*16];

__device__ __forceinline__ float ex2f(float x) {
    float r; asm("ex2.approx.f32 %0, %1;" : "=f"(r) : "f"(x)); return r;
}
__device__ __forceinline__ float siluf(float x) {
    return x / (1.0f + __expf(-x));
}
__device__ __forceinline__ bool ratio_fast(const float* a2) {
    bool ok = true;
    #pragma unroll
    for (int s = 1; s < 16; s++) {
        float want = (float)(s + 1) * a2[0];
        ok = ok && (fabsf(a2[s] - want) <= 1e-3f * fabsf(want));
    }
    return ok;
}
// dA[s] = p^(s+1): exponents of dA[(s-1)>>1] and dA[s>>1] sum to s+1
__device__ __forceinline__ void powers16(float p, float* dA) {
    dA[0] = p;
    #pragma unroll
    for (int s = 1; s < 16; s++) dA[s] = dA[(s-1) >> 1] * dA[s >> 1];
}

// smem layout offsets (floats)
#define XS_PITCH 68
#define XI_PITCH 132
#define OFF_XS    0
#define OFF_STAT  (35*XS_PITCH)              // 2380
#define OFF_WQ    (OFF_STAT + 72)            // 2452 ; Wq [64][68] or Ws [36][132]
#define WQ_SIZE   4752                        // max(64*68=4352, 36*132=4752)
#define OFF_XIS   (OFF_WQ + WQ_SIZE)         // 7204
#define OFF_R36   (OFF_XIS + 35*XI_PITCH)    // 11824
#define SMEMA_FLOATS (OFF_R36 + 32*36)       // 12976 -> 51904 B

// == KA: LN + W_in GEMM + conv/SiLU + x_proj + dt + CHUNK SCAN SUMMARY =======
// grid = 32 seq * 32 chunks (32 tokens + 3 halo), block = 128, dynamic smem
__global__ void __launch_bounds__(128, 4) kA_front(
    const float* __restrict__ x0, const float* __restrict__ x1,
    const float* __restrict__ x2, const float* __restrict__ x3,
    const float* __restrict__ ga, const float* __restrict__ gb,
    const float* __restrict__ gc, const float* __restrict__ gd,
    const float* __restrict__ ba, const float* __restrict__ bb,
    const float* __restrict__ bc_, const float* __restrict__ bd,
    const float* __restrict__ W_in,
    const float* __restrict__ W_conv, const float* __restrict__ b_conv,
    const float* __restrict__ W_xproj, const float* __restrict__ W_dt,
    const float* __restrict__ b_dt, const float* __restrict__ A_log)
{
    extern __shared__ float sm[];
    float* xs    = sm + OFF_XS;    // [35][68]
    float* stat  = sm + OFF_STAT;  // [35][2]
    float* Wq    = sm + OFF_WQ;    // [64][68] W_in quarter / [36][132] W_xproj^T
    float* xis   = sm + OFF_XIS;   // [35][132]; rows 0..31 become xc in place
    float* res36 = sm + OFF_R36;   // [32][36]

    int tid = threadIdx.x;
    int blk = blockIdx.x;
    int seq = blk >> 5;
    int ck  = blk & 31;
    int l0  = ck * 32;
    int br  = seq >> 3;
    int b   = seq & 7;

    const float* xp = (br == 0) ? x0 : (br == 1) ? x1 : (br == 2) ? x2 : x3;
    const float* gp = (br == 0) ? ga : (br == 1) ? gb : (br == 2) ? gc : gd;
    const float* bp = (br == 0) ? ba : (br == 1) ? bb : (br == 2) ? bc_ : bd;

    // ---- load 35 tokens x 64 channels (3-token halo) ----
    for (int idx = tid; idx < 35*64; idx += 128) {
        int t = idx % 35, c = idx / 35;
        int tl = l0 - 3 + t;
        xs[t*XS_PITCH + c] = (tl >= 0) ? xp[(size_t)(b*64 + c)*1024 + tl] : 0.f;
    }
    __syncthreads();
    if (tid < 35) {
        float s = 0.f, s2 = 0.f;
        #pragma unroll 8
        for (int c = 0; c < 64; c++) { float v = xs[tid*XS_PITCH + c]; s += v; s2 += v*v; }
        float m = s * (1.0f/64.0f);
        float var = s2 * (1.0f/64.0f) - m*m;
        stat[tid*2]   = m;
        stat[tid*2+1] = rsqrtf(var + 1e-5f);
    }
    __syncthreads();
    for (int idx = tid; idx < 35*64; idx += 128) {
        int c = idx & 63, t = idx >> 6;
        float v = (xs[t*XS_PITCH + c] - stat[t*2]) * stat[t*2+1] * gp[c] + bp[c];
        xs[t*XS_PITCH + c] = v;
        if (t >= 3) g_xn[(size_t)(seq*1024 + l0 - 3 + t)*64 + c] = v;
    }

    int tg = tid >> 5, jg = tid & 31;

    // ---- W_in GEMM in 4 quarters of 64 output rows; all smem reads float4 --
    #pragma unroll 1
    for (int q = 0; q < 4; q++) {
        __syncthreads();
        // load quarter: Wq[j'][c], pitch 68, via float4
        {
            const float4* Wg = (const float4*)(W_in + (size_t)q*64*64);
            #pragma unroll
            for (int r = 0; r < 8; r++) {
                int idx = r*128 + tid;           // 1024 float4s
                int j = idx >> 4, c4 = idx & 15;
                *(float4*)&Wq[j*XS_PITCH + c4*4] = Wg[j*16 + c4];
            }
        }
        __syncthreads();

        if (q < 2) {
            // xi quarter: 9 tokens per warp (halo range), 2 outputs per thread
            int t0 = tg * 9;
            int nt = (tg < 3) ? 9 : 8;
            float acc[9][2];
            #pragma unroll
            for (int i = 0; i < 9; i++) { acc[i][0] = 0.f; acc[i][1] = 0.f; }
            #pragma unroll 2
            for (int k4 = 0; k4 < 16; k4++) {
                float4 w0 = *(const float4*)&Wq[jg*XS_PITCH + k4*4];
                float4 w1 = *(const float4*)&Wq[(jg+32)*XS_PITCH + k4*4];
                #pragma unroll
                for (int i = 0; i < 9; i++) {
                    int t = t0 + i; if (t > 34) t = 34;
                    float4 xv = *(const float4*)&xs[t*XS_PITCH + k4*4];
                    acc[i][0] = fmaf(xv.x, w0.x, acc[i][0]);
                    acc[i][0] = fmaf(xv.y, w0.y, acc[i][0]);
                    acc[i][0] = fmaf(xv.z, w0.z, acc[i][0]);
                    acc[i][0] = fmaf(xv.w, w0.w, acc[i][0]);
                    acc[i][1] = fmaf(xv.x, w1.x, acc[i][1]);
                    acc[i][1] = fmaf(xv.y, w1.y, acc[i][1]);
                    acc[i][1] = fmaf(xv.z, w1.z, acc[i][1]);
                    acc[i][1] = fmaf(xv.w, w1.w, acc[i][1]);
                }
            }
            for (int i = 0; i < 9; i++) {
                int t = t0 + i;
                if (i < nt) {
                    bool valid = (l0 - 3 + t) >= 0;
                    xis[t*XI_PITCH + q*64 + jg]      = valid ? acc[i][0] : 0.f;
                    xis[t*XI_PITCH + q*64 + jg + 32] = valid ? acc[i][1] : 0.f;
                }
            }
        } else {
            // z quarter: 8 main tokens per warp
            int t0 = 3 + tg * 8;
            float acc[8][2];
            #pragma unroll
            for (int i = 0; i < 8; i++) { acc[i][0] = 0.f; acc[i][1] = 0.f; }
            #pragma unroll 2
            for (int k4 = 0; k4 < 16; k4++) {
                float4 w0 = *(const float4*)&Wq[jg*XS_PITCH + k4*4];
                float4 w1 = *(const float4*)&Wq[(jg+32)*XS_PITCH + k4*4];
                #pragma unroll
                for (int i = 0; i < 8; i++) {
                    float4 xv = *(const float4*)&xs[(t0+i)*XS_PITCH + k4*4];
                    acc[i][0] = fmaf(xv.x, w0.x, acc[i][0]);
                    acc[i][0] = fmaf(xv.y, w0.y, acc[i][0]);
                    acc[i][0] = fmaf(xv.z, w0.z, acc[i][0]);
                    acc[i][0] = fmaf(xv.w, w0.w, acc[i][0]);
                    acc[i][1] = fmaf(xv.x, w1.x, acc[i][1]);
                    acc[i][1] = fmaf(xv.y, w1.y, acc[i][1]);
                    acc[i][1] = fmaf(xv.z, w1.z, acc[i][1]);
                    acc[i][1] = fmaf(xv.w, w1.w, acc[i][1]);
                }
            }
            #pragma unroll
            for (int i = 0; i < 8; i++) {
                int tt = tg*8 + i;
                g_z[(size_t)(seq*1024 + l0 + tt)*128 + (q-2)*64 + jg]      = acc[i][0];
                g_z[(size_t)(seq*1024 + l0 + tt)*128 + (q-2)*64 + jg + 32] = acc[i][1];
            }
        }
    }
    __syncthreads();

    // ---- conv4 + SiLU, in place: row t of xis becomes xc[t] ----
    {
        int d = tid;
        float wc0 = W_conv[d*4+0], wc1 = W_conv[d*4+1], wc2 = W_conv[d*4+2], wc3 = W_conv[d*4+3];
        float bcv = b_conv[d];
        #pragma unroll 4
        for (int t = 0; t < 32; t++) {
            float v = bcv + wc0*xis[t*XI_PITCH + d] + wc1*xis[(t+1)*XI_PITCH + d]
                          + wc2*xis[(t+2)*XI_PITCH + d] + wc3*xis[(t+3)*XI_PITCH + d];
            v = siluf(v);
            xis[t*XI_PITCH + d] = v;  // safe: row t read only by iterations <= t
            g_xc[(size_t)(seq*1024 + l0 + t)*128 + d] = v;
        }
    }
    // ---- load W_xproj^T rows-along-dd: Ws[j][132], float4 copy ----
    {
        const float4* Wg = (const float4*)W_xproj;
        for (int idx = tid; idx < 36*32; idx += 128) {
            int j = idx >> 5, d4 = idx & 31;
            *(float4*)&Wq[j*XI_PITCH + d4*4] = Wg[j*32 + d4];
        }
    }
    __syncthreads();

    // ---- x_proj: 32 tokens x 36 outputs, float4 over dd ----
    for (int p = tid; p < 576; p += 128) {
        int tok = p / 18;
        int j0 = (p - tok*18) * 2;
        float a0 = 0.f, a1 = 0.f;
        #pragma unroll 8
        for (int d4 = 0; d4 < 32; d4++) {
            float4 xv = *(const float4*)&xis[tok*XI_PITCH + d4*4];
            float4 w0 = *(const float4*)&Wq[j0*XI_PITCH + d4*4];
            float4 w1 = *(const float4*)&Wq[(j0+1)*XI_PITCH + d4*4];
            a0 = fmaf(xv.x, w0.x, a0); a0 = fmaf(xv.y, w0.y, a0);
            a0 = fmaf(xv.z, w0.z, a0); a0 = fmaf(xv.w, w0.w, a0);
            a1 = fmaf(xv.x, w1.x, a1); a1 = fmaf(xv.y, w1.y, a1);
            a1 = fmaf(xv.z, w1.z, a1); a1 = fmaf(xv.w, w1.w, a1);
        }
        res36[tok*36 + j0]     = a0;
        res36[tok*36 + j0 + 1] = a1;
    }
    __syncthreads();

    // ---- fused: dt(softplus) + chunk scan summary (h0 = 0) ----
    {
        int d = tid;
        float wd0 = W_dt[d*4+0], wd1 = W_dt[d*4+1], wd2 = W_dt[d*4+2], wd3 = W_dt[d*4+3];
        float bdv = b_dt[d];
        float a2[16];
        #pragma unroll
        for (int s = 0; s < 16; s++) a2[s] = -__expf(A_log[d*16 + s]) * LOG2E;
        bool fast = ratio_fast(a2);
        float h[16];
        #pragma unroll
        for (int s = 0; s < 16; s++) h[s] = 0.f;
        float sdt = 0.f;

        for (int t = 0; t < 32; t++) {
            float4 r0 = *(const float4*)&res36[t*36];
            float raw = bdv + wd0*r0.x + wd1*r0.y + wd2*r0.z + wd3*r0.w;
            float sp = fmaxf(raw, 0.f) + log1pf(__expf(-fabsf(raw)));
            g_dt[(size_t)(seq*1024 + l0 + t)*128 + d] = sp;
            sdt += sp;
            float dx = sp * xis[t*XI_PITCH + d];
            float4 b0 = *(const float4*)&res36[t*36 + 4];
            float4 b1 = *(const float4*)&res36[t*36 + 8];
            float4 b2 = *(const float4*)&res36[t*36 + 12];
            float4 b3 = *(const float4*)&res36[t*36 + 16];
            const float bl[16] = {b0.x,b0.y,b0.z,b0.w, b1.x,b1.y,b1.z,b1.w,
                                  b2.x,b2.y,b2.z,b2.w, b3.x,b3.y,b3.z,b3.w};
            if (fast) {
                float p = ex2f(sp * a2[0]);
                float dA[16]; powers16(p, dA);
                #pragma unroll
                for (int s = 0; s < 16; s++)
                    h[s] = fmaf(dA[s], h[s], dx * bl[s]);
            } else {
                #pragma unroll
                for (int s = 0; s < 16; s++) {
                    float dA = ex2f(sp * a2[s]);
                    h[s] = fmaf(dA, h[s], dx * bl[s]);
                }
            }
        }
        size_t base = ((size_t)(seq*NCHK + ck)*128 + d)*16;
        if (fast) {
            float p = ex2f(a2[0] * sdt);
            float dA[16]; powers16(p, dA);
            #pragma unroll
            for (int s = 0; s < 16; s++) {
                g_pend[base + s] = h[s];
                g_dtot[base + s] = dA[s];
            }
        } else {
            #pragma unroll
            for (int s = 0; s < 16; s++) {
                g_pend[base + s] = h[s];
                g_dtot[base + s] = ex2f(a2[s] * sdt);
            }
        }
    }

    // ---- B/C scatter ----
    for (int idx = tid; idx < 1024; idx += 128) {
        int tok = idx >> 5, q = idx & 31;
        float v = res36[tok*36 + 4 + q];
        if (q < 16) g_Bm[(size_t)(seq*1024 + l0 + tok)*16 + q]        = v;
        else        g_Cm[(size_t)(seq*1024 + l0 + tok)*16 + (q - 16)] = v;
    }
}

// ============== K4: sequential combine of chunk states ======================
// grid = 256 (seq*8), block = 256; one thread per (seq, pair); two 16-batches
__global__ void __launch_bounds__(256) k4_combine()
{
    int blk = blockIdx.x;
    int seq = blk >> 3;
    int pair = (blk & 7) * 256 + threadIdx.x;
    float h = 0.f;
    #pragma unroll
    for (int half = 0; half < 2; half++) {
        float dtv[16], pev[16];
        #pragma unroll
        for (int k = 0; k < 16; k++) {
            size_t o = (size_t)(seq*NCHK + half*16 + k)*2048 + pair;
            dtv[k] = g_dtot[o];
            pev[k] = g_pend[o];
        }
        #pragma unroll
        for (int k = 0; k < 16; k++) {
            g_h0[(size_t)(seq*NCHK + half*16 + k)*2048 + pair] = h;
            h = fmaf(dtv[k], h, pev[k]);
        }
    }
}

// ====== KB: scan + y epilogue + W_out GEMM + skip + transposed output =======
// grid = 1024 (seq*NCHK + chunk), block = 128 (thread = channel d), dyn smem
__global__ void __launch_bounds__(128) kB_scan_out(
    const float* __restrict__ A_log, const float* __restrict__ Dp,
    const float* __restrict__ W_out, const float* __restrict__ skip,
    float* __restrict__ out)
{
    extern __shared__ float sm[];
    float* Bs  = sm;                 // [32][16]
    float* Cs  = Bs + CHKL*16;       // [32][16]
    float* ys  = Cs + CHKL*16;       // [32 t][129]  (reused as os [64 c][33])
    float* Wsh = ys + 32*129;        // [128 k][65 c]

    int tid = threadIdx.x;
    int blk = blockIdx.x;
    int seq = blk >> 5;
    int ck  = blk & 31;
    int c0  = ck * CHKL;
    int br  = seq >> 3;
    int b   = seq & 7;

    for (int idx = tid; idx < CHKL*16; idx += 128) {
        Bs[idx] = g_Bm[(size_t)(seq*1024 + c0)*16 + idx];
        Cs[idx] = g_Cm[(size_t)(seq*1024 + c0)*16 + idx];
    }
    for (int idx = tid; idx < 64*128; idx += 128) {
        int c = idx >> 7, k = idx & 127;
        Wsh[k*65 + c] = W_out[(size_t)c*128 + k];
    }
    __syncthreads();

    int d = tid;
    float a2[16];
    #pragma unroll
    for (int s = 0; s < 16; s++) a2[s] = -__expf(A_log[d*16 + s]) * LOG2E;
    bool fast = ratio_fast(a2);
    float Dv = Dp[d];

    float h[16];
    size_t hb = ((size_t)(seq*NCHK + ck)*128 + d)*16;
    #pragma unroll
    for (int s = 0; s < 16; s++) h[s] = g_h0[hb + s];

    const float* dtp_ = g_dt + (size_t)(seq*1024 + c0)*128 + d;
    const float* xcp_ = g_xc + (size_t)(seq*1024 + c0)*128 + d;
    const float* zp_  = g_z  + (size_t)(seq*1024 + c0)*128 + d;

    if (fast) {
        const float4* B4 = (const float4*)Bs;
        const float4* C4 = (const float4*)Cs;
        float pdt[4], pxc[4], pz[4];
        #pragma unroll
        for (int j = 0; j < 4; j++) {
            pdt[j] = dtp_[j*128]; pxc[j] = xcp_[j*128]; pz[j] = zp_[j*128];
        }
        for (int t0 = 0; t0 < CHKL; t0 += 4) {
            float ndt[4], nxc[4], nz[4];
            #pragma unroll
            for (int j = 0; j < 4; j++) {
                int tn = t0 + 4 + j;
                if (tn < CHKL) { ndt[j] = dtp_[tn*128]; nxc[j] = xcp_[tn*128]; nz[j] = zp_[tn*128]; }
                else           { ndt[j] = 0.f; nxc[j] = 0.f; nz[j] = 0.f; }
            }
            #pragma unroll
            for (int j = 0; j < 4; j++) {
                int t = t0 + j;
                float dx = pdt[j] * pxc[j];
                float p = ex2f(pdt[j] * a2[0]);
                float dA[16]; powers16(p, dA);
                float4 b0 = B4[t*4+0], b1 = B4[t*4+1], b2 = B4[t*4+2], b3 = B4[t*4+3];
                float4 cc0 = C4[t*4+0], cc1 = C4[t*4+1], cc2 = C4[t*4+2], cc3 = C4[t*4+3];
                const float bl[16] = {b0.x,b0.y,b0.z,b0.w, b1.x,b1.y,b1.z,b1.w,
                                      b2.x,b2.y,b2.z,b2.w, b3.x,b3.y,b3.z,b3.w};
                const float cl[16] = {cc0.x,cc0.y,cc0.z,cc0.w, cc1.x,cc1.y,cc1.z,cc1.w,
                                      cc2.x,cc2.y,cc2.z,cc2.w, cc3.x,cc3.y,cc3.z,cc3.w};
                float y = 0.f;
                #pragma unroll
                for (int s = 0; s < 16; s++) {
                    h[s] = fmaf(dA[s], h[s], dx * bl[s]);
                    y = fmaf(h[s], cl[s], y);
                }
                ys[t*129 + d] = (y + Dv*pxc[j]) * siluf(pz[j]);
            }
            #pragma unroll
            for (int j = 0; j < 4; j++) { pdt[j] = ndt[j]; pxc[j] = nxc[j]; pz[j] = nz[j]; }
        }
    } else {
        for (int t = 0; t < CHKL; t++) {
            float dtv = dtp_[t*128], xcv = xcp_[t*128], zv = zp_[t*128];
            float dx = dtv * xcv;
            float y = 0.f;
            #pragma unroll
            for (int s = 0; s < 16; s++) {
                float dA = ex2f(dtv * a2[s]);
                h[s] = fmaf(dA, h[s], dx * Bs[t*16 + s]);
                y = fmaf(h[s], Cs[t*16 + s], y);
            }
            ys[t*129 + d] = (y + Dv*xcv) * siluf(zv);
        }
    }
    __syncthreads();

    // ---- W_out GEMM (32 tok x 64 out x 128 k) ----
    int tg = tid >> 4, jg = tid & 15;
    float acc[4][4];
    #pragma unroll
    for (int i = 0; i < 4; i++)
        #pragma unroll
        for (int u = 0; u < 4; u++) acc[i][u] = 0.f;
    #pragma unroll 4
    for (int k = 0; k < 128; k++) {
        float xv[4];
        #pragma unroll
        for (int i = 0; i < 4; i++) xv[i] = ys[(tg*4 + i)*129 + k];
        #pragma unroll
        for (int u = 0; u < 4; u++) {
            float w = Wsh[k*65 + jg + 16*u];
            #pragma unroll
            for (int i = 0; i < 4; i++) acc[i][u] = fmaf(xv[i], w, acc[i][u]);
        }
    }
    __syncthreads();
    float* os = ys;   // reuse: [c][t] pitch 33
    float sk = skip[0];
    #pragma unroll
    for (int u = 0; u < 4; u++)
        #pragma unroll
        for (int i = 0; i < 4; i++) {
            int t = tg*4 + i, c = jg + 16*u;
            float xnv = g_xn[(size_t)(seq*1024 + c0 + t)*64 + c];
            os[c*33 + t] = acc[i][u] + sk * xnv;
        }
    __syncthreads();
    for (int idx = tid; idx < 2048; idx += 128) {
        int c = idx >> 5, t = idx & 31;
        out[(size_t)(b*256 + br*64 + c)*1024 + c0 + t] = os[c*33 + t];
    }
}

// ============================== launch ======================================
extern "C" void kernel_launch(void* const* d_in, const int* in_sizes, int n_in,
                              void* d_out, int out_size) {
    const float* x0      = (const float*)d_in[0];
    const float* x1      = (const float*)d_in[1];
    const float* x2      = (const float*)d_in[2];
    const float* x3      = (const float*)d_in[3];
    const float* g1      = (const float*)d_in[4];
    const float* be1     = (const float*)d_in[5];
    const float* g2      = (const float*)d_in[6];
    const float* be2     = (const float*)d_in[7];
    const float* g3      = (const float*)d_in[8];
    const float* be3     = (const float*)d_in[9];
    const float* g4      = (const float*)d_in[10];
    const float* be4     = (const float*)d_in[11];
    const float* skip    = (const float*)d_in[12];
    const float* W_in    = (const float*)d_in[13];
    const float* W_conv  = (const float*)d_in[14];
    const float* b_conv  = (const float*)d_in[15];
    const float* W_xproj = (const float*)d_in[16];
    const float* W_dt    = (const float*)d_in[17];
    const float* b_dt    = (const float*)d_in[18];
    const float* A_log   = (const float*)d_in[19];
    const float* Dp      = (const float*)d_in[20];
    const float* W_out   = (const float*)d_in[21];
    float* out = (float*)d_out;

    const int SMEMA = SMEMA_FLOATS * (int)sizeof(float);
    const int SMEMB = (CHKL*16*2 + 32*129 + 128*65) * (int)sizeof(float);
    static bool configured = false;
    if (!configured) {
        cudaFuncSetAttribute(kA_front,
                             cudaFuncAttributeMaxDynamicSharedMemorySize, SMEMA);
        cudaFuncSetAttribute(kB_scan_out,
                             cudaFuncAttributeMaxDynamicSharedMemorySize, SMEMB);
        configured = true;
    }

    kA_front<<<1024, 128, SMEMA>>>(x0, x1, x2, x3, g1, g2, g3, g4,
                                   be1, be2, be3, be4, W_in,
                                   W_conv, b_conv, W_xproj, W_dt, b_dt, A_log);
    k4_combine<<<256, 256>>>();
    kB_scan_out<<<1024, 128, SMEMB>>>(A_log, Dp, W_out, skip, out);
}